// round 13
// baseline (speedup 1.0000x reference)
#include <cuda_runtime.h>
#include <cuda_bf16.h>
#include <cstdint>
#include <cstddef>

#define HID 1024
#define NB 128
#define TSTEPS 256
#define HORIZON 24
#define NCTA 128
#define NTHR 512
#define HP 512                 // bf16x2 (hi,lo) pairs per 1024-wide row
#define XP 16                  // pairs in x/pred block (32 k, zero padded)
#define P0 (XP + HP)           // 528 pairs  : enc0/dec0 K
#define P1 (2 * HP)            // 1024 pairs : enc1/dec1 K

// ---------------- persistent scratch (__device__ globals; no allocs) -------------
// weights: [interleaved_col (4j+g)][pair] as uint2(hi bf16x2, lo bf16x2)
__device__ __align__(16) uint2 g_We0[(size_t)4096 * P0];
__device__ __align__(16) uint2 g_We1[(size_t)4096 * P1];
__device__ __align__(16) uint2 g_Wd0[(size_t)4096 * P0];
__device__ __align__(16) uint2 g_Wd1[(size_t)4096 * P1];
// activations as split pairs
__device__ __align__(16) uint2 g_ys0p[(size_t)TSTEPS * NB * HP];
__device__ __align__(16) uint2 g_hBp[2 * NB * HP];
__device__ __align__(16) uint2 g_hd0p[2 * NB * HP];
__device__ __align__(16) uint2 g_hd1p[2 * NB * HP];
__device__ __align__(16) uint2 g_zerop[NB * HP];
__device__ __align__(16) uint2 g_xp[(size_t)TSTEPS * NB * XP];
__device__ __align__(16) uint2 g_predp[NB * XP];
__device__ float g_c0[NB * HID];
__device__ float g_c1[NB * HID];
__device__ unsigned g_bar_cnt;
__device__ volatile unsigned g_bar_epoch;

// ---------------- helpers --------------------------------------------------------
__device__ __forceinline__ uint32_t bf2pack(float hi, float lo) {
  uint32_t r;
  asm("cvt.rn.bf16x2.f32 %0, %1, %2;" : "=r"(r) : "f"(hi), "f"(lo));
  return r;
}
__device__ __forceinline__ uint2 split2(float v0, float v1) {
  uint32_t hp = bf2pack(v1, v0);
  float h0 = __uint_as_float(hp << 16);
  float h1 = __uint_as_float(hp & 0xFFFF0000u);
  uint32_t lp = bf2pack(v1 - h1, v0 - h0);
  return make_uint2(hp, lp);
}
__device__ __forceinline__ void mma_bf16(float d[4], const uint32_t a[4], const uint32_t b[2]) {
  asm volatile(
      "mma.sync.aligned.m16n8k16.row.col.f32.bf16.bf16.f32 "
      "{%0,%1,%2,%3}, {%4,%5,%6,%7}, {%8,%9}, {%0,%1,%2,%3};\n"
      : "+f"(d[0]), "+f"(d[1]), "+f"(d[2]), "+f"(d[3])
      : "r"(a[0]), "r"(a[1]), "r"(a[2]), "r"(a[3]), "r"(b[0]), "r"(b[1]));
}
__device__ __forceinline__ float sigmoidf_(float x) { return 1.f / (1.f + expf(-x)); }

__device__ __forceinline__ uint32_t smem_u32(const void* p) {
  uint32_t a;
  asm("{ .reg .u64 t; cvta.to.shared.u64 t, %1; cvt.u32.u64 %0, t; }" : "=r"(a) : "l"(p));
  return a;
}
#define CP_ASYNC16(dst, src) \
  asm volatile("cp.async.cg.shared.global [%0], [%1], 16;" :: "r"(dst), "l"(src) : "memory")
#define CP_COMMIT() asm volatile("cp.async.commit_group;" ::: "memory")
#define CP_WAIT1()  asm volatile("cp.async.wait_group 1;" ::: "memory")
#define CP_WAIT0()  asm volatile("cp.async.wait_group 0;" ::: "memory")

// ---------------- persistent kernel ----------------------------------------------
// 128 CTAs: mBase=(bx>>6)*64, nBase=(bx&63)*64. 16 warps: wk=wid&1 (K half),
// wn=(wid>>1)&3 (N 16-col slice), wm=wid>>3 (M half) -> warp tile 32x16,
// acc[2][2][4] = 16 regs. Super = 2 chunks of K=16; 2 stages x 2 chunks = 4 slots.
// Staging: tid<256 -> A quads, tid>=256 -> B quads (1 cp.async each per chunk).
// XOR swizzle f(r)=(r&2)*2, stride 8 uint2/row, 32KB static smem.
__global__ void __launch_bounds__(NTHR, 1) lstm_persist(
    const float* __restrict__ eb0, const float* __restrict__ eb1,
    const float* __restrict__ db0, const float* __restrict__ db1,
    const float* __restrict__ projW, const float* __restrict__ projb,
    float* __restrict__ out)
{
  __shared__ __align__(16) uint2 sA[4 * 64 * 8];    // 16384 B
  __shared__ __align__(16) uint2 sB[4 * 64 * 8];    // 16384 B
  float* red = reinterpret_cast<float*>(sA);        // overlay (post-drain only)

  const int tid  = threadIdx.x;
  const int lane = tid & 31;
  const int wid  = tid >> 5;                 // 0..15
  const int wk   = wid & 1;
  const int wn   = (wid >> 1) & 3;
  const int wm   = wid >> 3;
  const int gid  = lane >> 2;
  const int q    = lane & 3;
  const int bx   = blockIdx.x;
  const int mBase = (bx >> 6) * 64;
  const int nBase = (bx & 63) * 64;

  // staging map: tid<256 stages A, tid>=256 stages B. row 0..63, 16B quad.
  const int isA   = (tid < 256) ? 1 : 0;
  const int stid  = tid & 255;
  const int sRow  = stid >> 2;
  const int quad2 = (stid & 3) * 2;
  const int fS    = (sRow & 2) * 2;
  const int mG    = mBase + sRow;
  const int colB  = nBase + sRow;

  const uint32_t sAu = smem_u32(sA);
  const uint32_t sBu = smem_u32(sB);

  unsigned barNo = 0;
  auto grid_barrier = [&]() {
    ++barNo;
    __threadfence();
    __syncthreads();
    if (tid == 0) {
      unsigned old = atomicAdd(&g_bar_cnt, 1u);
      if (old == NCTA - 1) {
        g_bar_cnt = 0;
        __threadfence();
        g_bar_epoch = barNo;
      } else {
        while (g_bar_epoch < barNo) __nanosleep(32);
      }
    }
    __syncthreads();
    __threadfence();
  };

  auto step = [&](const uint2* __restrict__ Apx, int pxStride, int pxPairs,
                  const uint2* __restrict__ Ahp,
                  const uint2* __restrict__ gW, int P,
                  const float* __restrict__ bias, float* __restrict__ cS,
                  uint2* __restrict__ hOutP) {
    const int S = P >> 4;                      // supers of 2 chunks
    const size_t bWoff = (size_t)colB * P;

    auto ISSUE = [&](int si, int st) {
#pragma unroll
      for (int u = 0; u < 2; ++u) {
        const int kb = si * 2 + u;
        const int gp = kb * 8 + quad2;
        if (isA) {
          const uint2* asrc = (gp < pxPairs)
              ? (Apx + (size_t)mG * pxStride + gp)
              : (Ahp + (size_t)mG * HP + (gp - pxPairs));
          const uint32_t dA = sAu + (((st * 2 + u) * 64 + sRow) * 8 + (quad2 ^ fS)) * 8;
          CP_ASYNC16(dA, asrc);
        } else {
          const uint32_t dB = sBu + (((st * 2 + u) * 64 + sRow) * 8 + (quad2 ^ fS)) * 8;
          CP_ASYNC16(dB, gW + bWoff + gp);
        }
      }
    };

    float acc[2][2][4];
#pragma unroll
    for (int a = 0; a < 2; ++a)
#pragma unroll
      for (int b = 0; b < 2; ++b)
#pragma unroll
        for (int c = 0; c < 4; ++c) acc[a][b][c] = 0.f;

    ISSUE(0, 0); CP_COMMIT();
    ISSUE(1, 1); CP_COMMIT();
    CP_WAIT1();                        // stage 0 (group 0) complete
    __syncthreads();

    for (int s = 0; s < S; ++s) {
      const int st = s & 1;
      const uint2* As = sA + (st * 2 + wk) * 512;
      const uint2* Bs = sB + (st * 2 + wk) * 512;
      uint32_t aH[2][4], aL[2][4], bH[2][2], bL[2][2];
#pragma unroll
      for (int mt = 0; mt < 2; ++mt) {
        const int r = wm * 32 + mt * 16 + gid;
        const int fr = (r & 2) * 2;
        const uint2 u0 = As[r * 8 + (q ^ fr)];
        const uint2 u1 = As[(r + 8) * 8 + (q ^ fr)];
        const uint2 u2 = As[r * 8 + ((q + 4) ^ fr)];
        const uint2 u3 = As[(r + 8) * 8 + ((q + 4) ^ fr)];
        aH[mt][0] = u0.x; aH[mt][1] = u1.x; aH[mt][2] = u2.x; aH[mt][3] = u3.x;
        aL[mt][0] = u0.y; aL[mt][1] = u1.y; aL[mt][2] = u2.y; aL[mt][3] = u3.y;
      }
#pragma unroll
      for (int nt = 0; nt < 2; ++nt) {
        const int n = wn * 16 + nt * 8 + gid;
        const int fn = (n & 2) * 2;
        const uint2 v0 = Bs[n * 8 + (q ^ fn)];
        const uint2 v1 = Bs[n * 8 + ((q + 4) ^ fn)];
        bH[nt][0] = v0.x; bH[nt][1] = v1.x;
        bL[nt][0] = v0.y; bL[nt][1] = v1.y;
      }
      __syncthreads();                 // all reads of stage st done
      if (s + 2 < S) ISSUE(s + 2, st); // refill this stage for super s+2
      CP_COMMIT();
#pragma unroll
      for (int mt = 0; mt < 2; ++mt)
#pragma unroll
        for (int nt = 0; nt < 2; ++nt) {
          mma_bf16(acc[mt][nt], aL[mt], bH[nt]);
          mma_bf16(acc[mt][nt], aH[mt], bL[nt]);
          mma_bf16(acc[mt][nt], aH[mt], bH[nt]);
        }
      CP_WAIT1();                      // next stage's group complete
      __syncthreads();
    }
    CP_WAIT0();
    __syncthreads();

    // ---- split-K reduction: wk==1 hands 16 accs to wk==0 partner ----
    float* af = &acc[0][0][0];
    const int slotr = (((wid >> 1) * 32) + lane) * 16;
    if (wk) {
#pragma unroll
      for (int i = 0; i < 16; ++i) red[slotr + i] = af[i];
    }
    __syncthreads();
    if (!wk) {
#pragma unroll
      for (int i = 0; i < 16; ++i) af[i] += red[slotr + i];

      // ---- epilogue: bias + activations + c update + paired-h store ----
      const int cWarp = nBase + wn * 16;
      const int mWarp = mBase + wm * 32;
#pragma unroll
      for (int mt = 0; mt < 2; ++mt) {
#pragma unroll
        for (int nt = 0; nt < 2; ++nt) {
          const float p0 = __shfl_xor_sync(0xffffffffu, acc[mt][nt][0], 1);
          const float p1 = __shfl_xor_sync(0xffffffffu, acc[mt][nt][1], 1);
          const float p2 = __shfl_xor_sync(0xffffffffu, acc[mt][nt][2], 1);
          const float p3 = __shfl_xor_sync(0xffffffffu, acc[mt][nt][3], 1);
          const int cg = cWarp + nt * 8 + 2 * q;
          const int j  = cg >> 2;                 // odd lanes: unused values
          const float bi = bias[j];
          const float bf = bias[HID + j];
          const float bg = bias[2 * HID + j];
          const float bo = bias[3 * HID + j];
          const int r0 = mWarp + mt * 16 + gid;
          const int r1 = r0 + 8;
          float hn0, hn1;
          {
            const float ig = sigmoidf_(acc[mt][nt][0] + bi);
            const float fg = sigmoidf_(acc[mt][nt][1] + bf);
            const float gg = tanhf(p0 + bg);
            const float og = sigmoidf_(p1 + bo);
            const float cn = fg * cS[r0 * HID + j] + ig * gg;
            if ((lane & 1) == 0) cS[r0 * HID + j] = cn;
            hn0 = og * tanhf(cn);
          }
          {
            const float ig = sigmoidf_(acc[mt][nt][2] + bi);
            const float fg = sigmoidf_(acc[mt][nt][3] + bf);
            const float gg = tanhf(p2 + bg);
            const float og = sigmoidf_(p3 + bo);
            const float cn = fg * cS[r1 * HID + j] + ig * gg;
            if ((lane & 1) == 0) cS[r1 * HID + j] = cn;
            hn1 = og * tanhf(cn);
          }
          const float x0 = __shfl_xor_sync(0xffffffffu, hn0, 2);
          const float x1 = __shfl_xor_sync(0xffffffffu, hn1, 2);
          if (q == 0) {
            const int jp = (cWarp + nt * 8) >> 3;
            hOutP[(size_t)r0 * HP + jp] = split2(hn0, x0);
            hOutP[(size_t)r1 * HP + jp] = split2(hn1, x1);
          }
        }
      }
    }
  };

  const size_t HS = (size_t)NB * HP;

  // -------- encoder layer 0 --------
  for (int t = 0; t < TSTEPS; ++t) {
    const uint2* ah = t ? (g_ys0p + (size_t)(t - 1) * HS) : g_zerop;
    step(g_xp + (size_t)t * NB * XP, XP, XP, ah, g_We0, P0, eb0, g_c0,
         g_ys0p + (size_t)t * HS);
    grid_barrier();
  }
  // -------- encoder layer 1 --------
  for (int t = 0; t < TSTEPS; ++t) {
    const int cur = t & 1, prv = (t - 1) & 1;
    const uint2* ah = t ? (g_hBp + (size_t)prv * HS) : g_zerop;
    step(g_ys0p + (size_t)t * HS, HP, HP, ah, g_We1, P1, eb1, g_c1,
         g_hBp + (size_t)cur * HS);
    grid_barrier();
  }
  // -------- decoder --------
  for (int t = 0; t < HORIZON; ++t) {
    const int cur = t & 1, prv = (t - 1) & 1;
    const uint2* ah0 = t ? (g_hd0p + (size_t)prv * HS)
                         : (g_ys0p + (size_t)(TSTEPS - 1) * HS);
    step(g_predp, XP, XP, ah0, g_Wd0, P0, db0, g_c0, g_hd0p + (size_t)cur * HS);
    grid_barrier();
    const uint2* ah1 = t ? (g_hd1p + (size_t)prv * HS) : (g_hBp + HS);
    step(g_hd0p + (size_t)cur * HS, HP, HP, ah1, g_Wd1, P1, db1, g_c1,
         g_hd1p + (size_t)cur * HS);
    grid_barrier();
    // projection: CTA bx handles batch row bx
    {
      const uint2* hr = g_hd1p + (size_t)cur * HS + (size_t)bx * HP;
      float s = 0.f;
      for (int p = tid; p < HP; p += NTHR) {
        const uint2 u = hr[p];
        const float v0 = __uint_as_float(u.x << 16) + __uint_as_float(u.y << 16);
        const float v1 = __uint_as_float(u.x & 0xFFFF0000u) +
                         __uint_as_float(u.y & 0xFFFF0000u);
        s += v0 * projW[2 * p] + v1 * projW[2 * p + 1];
      }
#pragma unroll
      for (int o = 16; o; o >>= 1) s += __shfl_xor_sync(0xffffffffu, s, o);
      if (lane == 0) red[wid] = s;
      __syncthreads();
      if (tid == 0) {
        float tot = 0.f;
#pragma unroll
        for (int i = 0; i < 16; ++i) tot += red[i];
        const float p = tot + projb[0];
        out[bx * HORIZON + t] = p;
        g_predp[bx * XP] = split2(p, 0.f);
      }
      __syncthreads();
    }
    grid_barrier();
  }
}

// ---------------- init: weight split/interleave + staging + zeros ----------------
__global__ void init_kernel(
    const float* __restrict__ x,
    const float* __restrict__ eWih0, const float* __restrict__ eWhh0,
    const float* __restrict__ eWih1, const float* __restrict__ eWhh1,
    const float* __restrict__ dWih0, const float* __restrict__ dWhh0,
    const float* __restrict__ dWih1, const float* __restrict__ dWhh1)
{
  const int nthreads = gridDim.x * blockDim.x;
  const int tid0 = blockIdx.x * blockDim.x + threadIdx.x;
  if (tid0 == 0) { g_bar_cnt = 0; g_bar_epoch = 0; }

  for (size_t i = tid0; i < (size_t)4096 * P0; i += nthreads) {
    const int c = (int)(i / P0);
    const int p = (int)(i % P0);
    const int orow = (c & 3) * HID + (c >> 2);
    const int k = 2 * p;
    float e0a, e0b, d0a, d0b;
    if (k < 32) {
      e0a = (k < 8) ? eWih0[orow * 8 + k] : 0.f;
      e0b = (k + 1 < 8) ? eWih0[orow * 8 + k + 1] : 0.f;
      d0a = (k == 0) ? dWih0[orow] : 0.f;
      d0b = 0.f;
    } else {
      e0a = eWhh0[(size_t)orow * HID + (k - 32)];
      e0b = eWhh0[(size_t)orow * HID + (k - 31)];
      d0a = dWhh0[(size_t)orow * HID + (k - 32)];
      d0b = dWhh0[(size_t)orow * HID + (k - 31)];
    }
    g_We0[i] = split2(e0a, e0b);
    g_Wd0[i] = split2(d0a, d0b);
  }
  for (size_t i = tid0; i < (size_t)4096 * P1; i += nthreads) {
    const int c = (int)(i / P1);
    const int p = (int)(i % P1);
    const int orow = (c & 3) * HID + (c >> 2);
    const int k = 2 * p;
    float e1a, e1b, d1a, d1b;
    if (k < HID) {
      e1a = eWih1[(size_t)orow * HID + k];
      e1b = eWih1[(size_t)orow * HID + k + 1];
      d1a = dWih1[(size_t)orow * HID + k];
      d1b = dWih1[(size_t)orow * HID + k + 1];
    } else {
      e1a = eWhh1[(size_t)orow * HID + (k - HID)];
      e1b = eWhh1[(size_t)orow * HID + (k - HID + 1)];
      d1a = dWhh1[(size_t)orow * HID + (k - HID)];
      d1b = dWhh1[(size_t)orow * HID + (k - HID + 1)];
    }
    g_We1[i] = split2(e1a, e1b);
    g_Wd1[i] = split2(d1a, d1b);
  }
  for (size_t i = tid0; i < (size_t)TSTEPS * NB * XP; i += nthreads) {
    const int p = (int)(i & (XP - 1));
    const int m = (int)((i >> 4) & (NB - 1));
    const int t = (int)(i >> 11);
    const int k = 2 * p;
    const float v0 = (k < 8) ? x[((size_t)m * TSTEPS + t) * 8 + k] : 0.f;
    const float v1 = (k + 1 < 8) ? x[((size_t)m * TSTEPS + t) * 8 + k + 1] : 0.f;
    g_xp[i] = split2(v0, v1);
  }
  for (int i = tid0; i < NB * XP; i += nthreads) {
    const int m = i >> 4;
    const int p = i & (XP - 1);
    g_predp[i] = (p == 0)
        ? split2(x[((size_t)m * TSTEPS + (TSTEPS - 1)) * 8], 0.f)
        : make_uint2(0u, 0u);
  }
  for (int i = tid0; i < NB * HP; i += nthreads) g_zerop[i] = make_uint2(0u, 0u);
  for (int i = tid0; i < NB * HID; i += nthreads) { g_c0[i] = 0.f; g_c1[i] = 0.f; }
}

// ---------------- host side ------------------------------------------------------
extern "C" void kernel_launch(void* const* d_in, const int* in_sizes, int n_in,
                              void* d_out, int out_size) {
  const float* x     = (const float*)d_in[0];
  const float* eWih0 = (const float*)d_in[1];
  const float* eWhh0 = (const float*)d_in[2];
  const float* eb0   = (const float*)d_in[3];
  const float* eWih1 = (const float*)d_in[4];
  const float* eWhh1 = (const float*)d_in[5];
  const float* eb1   = (const float*)d_in[6];
  const float* dWih0 = (const float*)d_in[7];
  const float* dWhh0 = (const float*)d_in[8];
  const float* db0   = (const float*)d_in[9];
  const float* dWih1 = (const float*)d_in[10];
  const float* dWhh1 = (const float*)d_in[11];
  const float* db1   = (const float*)d_in[12];
  const float* projW = (const float*)d_in[13];
  const float* projb = (const float*)d_in[14];
  float* out = (float*)d_out;

  init_kernel<<<4096, 512>>>(x, eWih0, eWhh0, eWih1, eWhh1,
                             dWih0, dWhh0, dWih1, dWhh1);
  lstm_persist<<<NCTA, NTHR>>>(eb0, eb1, db0, db1, projW, projb, out);
}

// round 16
// speedup vs baseline: 1.4859x; 1.4859x over previous
#include <cuda_runtime.h>
#include <cstdint>
#include <cstddef>

#define HID 1024
#define NB 128
#define TSTEPS 256
#define HORIZON 24
#define NCTA 128
#define NTHR 256
#define HQ 256                 // s8 quads (4 elems) per 1024-wide h row
#define Q1 512                 // quads per row for K=2048 matrices

// ---------------- persistent scratch (__device__ globals; no allocs) -------------
// weights quantized: [interleaved col (4j+g)][quad] uint2 = (digit1 x4 s8, digit2 x4 s8)
__device__ __align__(16) uint2 g_Wq_e0[(size_t)4096 * HQ];
__device__ __align__(16) uint2 g_Wq_e1[(size_t)4096 * Q1];
__device__ __align__(16) uint2 g_Wq_d0[(size_t)4096 * HQ];
__device__ __align__(16) uint2 g_Wq_d1[(size_t)4096 * Q1];
__device__ float g_scW[4 * 4096];   // per-row |w|max per matrix (e0,e1,d0,d1)
// x-path float weights (gate-interleaved) + float x / pred
__device__ float g_We0xF[4096 * 8];
__device__ float g_Wd0xF[4096];
__device__ float g_xf[(size_t)TSTEPS * NB * 8];
__device__ float g_predf[NB];
// activations quantized as dual-digit s8 quads
__device__ __align__(16) uint2 g_ys0q[(size_t)TSTEPS * NB * HQ];
__device__ __align__(16) uint2 g_hBq[2 * NB * HQ];
__device__ __align__(16) uint2 g_hd0q[2 * NB * HQ];
__device__ __align__(16) uint2 g_hd1q[2 * NB * HQ];
__device__ __align__(16) uint2 g_zq[NB * HQ];
__device__ float g_c0[NB * HID];
__device__ float g_c1[NB * HID];
__device__ unsigned g_bar_cnt;
__device__ volatile unsigned g_bar_epoch;

// ---------------- helpers --------------------------------------------------------
__device__ __forceinline__ void mma_s8(int d[4], const uint32_t a[4], const uint32_t b[2]) {
  asm volatile(
      "mma.sync.aligned.m16n8k32.row.col.s32.s8.s8.s32 "
      "{%0,%1,%2,%3}, {%4,%5,%6,%7}, {%8,%9}, {%0,%1,%2,%3};\n"
      : "+r"(d[0]), "+r"(d[1]), "+r"(d[2]), "+r"(d[3])
      : "r"(a[0]), "r"(a[1]), "r"(a[2]), "r"(a[3]), "r"(b[0]), "r"(b[1]));
}
__device__ __forceinline__ float sigmoidf_(float x) { return 1.f / (1.f + expf(-x)); }

// quantize 4 pre-scaled values (|t|<=127) into (digit1, digit2) packed s8x4
__device__ __forceinline__ uint2 q4pack(float t0, float t1, float t2, float t3) {
  const int a0 = __float2int_rn(t0), a1 = __float2int_rn(t1);
  const int a2 = __float2int_rn(t2), a3 = __float2int_rn(t3);
  const int b0 = __float2int_rn((t0 - (float)a0) * 254.f);
  const int b1 = __float2int_rn((t1 - (float)a1) * 254.f);
  const int b2 = __float2int_rn((t2 - (float)a2) * 254.f);
  const int b3 = __float2int_rn((t3 - (float)a3) * 254.f);
  uint2 r;
  r.x = (uint32_t)(a0 & 255) | ((uint32_t)(a1 & 255) << 8) |
        ((uint32_t)(a2 & 255) << 16) | ((uint32_t)(a3 & 255) << 24);
  r.y = (uint32_t)(b0 & 255) | ((uint32_t)(b1 & 255) << 8) |
        ((uint32_t)(b2 & 255) << 16) | ((uint32_t)(b3 & 255) << 24);
  return r;
}
__device__ __forceinline__ int s8at(uint32_t u, int i) {
  return ((int)(u << (24 - 8 * i))) >> 24;
}
__device__ __forceinline__ uint32_t smem_u32(const void* p) {
  uint32_t a;
  asm("{ .reg .u64 t; cvta.to.shared.u64 t, %1; cvt.u32.u64 %0, t; }" : "=r"(a) : "l"(p));
  return a;
}
#define CP_ASYNC16(dst, src) \
  asm volatile("cp.async.cg.shared.global [%0], [%1], 16;" :: "r"(dst), "l"(src) : "memory")
#define CP_COMMIT() asm volatile("cp.async.commit_group;" ::: "memory")
#define CP_WAIT1()  asm volatile("cp.async.wait_group 1;" ::: "memory")
#define CP_WAIT0()  asm volatile("cp.async.wait_group 0;" ::: "memory")

// ---------------- persistent kernel ----------------------------------------------
// 128 CTAs: mBase=(bx>>6)*64, nBase=(bx&63)*64. 8 warps: wk=wid&1 (K half),
// wn=(wid>>1)&1, wm=wid>>2 -> warp tile 32x32. Chunk = K=32 s8 = 8 quads;
// super = 2 chunks; 2 stages x 2 chunks = 4 smem slots (R11-proven discipline).
// Dual-digit s8: acc1 += a1*b1; acc2 += a1*b2 + a2*b1 (a2*b2 dropped).
__global__ void __launch_bounds__(NTHR, 1) lstm_persist(
    const float* __restrict__ eb0, const float* __restrict__ eb1,
    const float* __restrict__ db0, const float* __restrict__ db1,
    const float* __restrict__ projW, const float* __restrict__ projb,
    float* __restrict__ out)
{
  __shared__ __align__(16) uint2 sA[4 * 64 * 8];    // 16384 B
  __shared__ __align__(16) uint2 sB[4 * 64 * 8];    // 16384 B
  int* redA = reinterpret_cast<int*>(sA);           // overlays (post-drain only)
  int* redB = reinterpret_cast<int*>(sB);
  float* redF = reinterpret_cast<float*>(sA);

  const int tid  = threadIdx.x;
  const int lane = tid & 31;
  const int wid  = tid >> 5;
  const int wk   = wid & 1;
  const int wn   = (wid >> 1) & 1;
  const int wm   = wid >> 2;
  const int gid  = lane >> 2;
  const int q    = lane & 3;
  const int bx   = blockIdx.x;
  const int mBase = (bx >> 6) * 64;
  const int nBase = (bx & 63) * 64;

  // staging map: thread -> row (0..63), 16B (2 quads)
  const int aRow  = tid >> 2;
  const int quad2 = (tid & 3) * 2;
  const int fS    = (aRow & 2) * 2;
  const int mG    = mBase + aRow;
  const int colB  = nBase + aRow;

  const uint32_t sAu = smem_u32(sA);
  const uint32_t sBu = smem_u32(sB);

  unsigned barNo = 0;
  auto grid_barrier = [&]() {
    ++barNo;
    __threadfence();
    __syncthreads();
    if (tid == 0) {
      unsigned old = atomicAdd(&g_bar_cnt, 1u);
      if (old == NCTA - 1) {
        g_bar_cnt = 0;
        __threadfence();
        g_bar_epoch = barNo;
      } else {
        while (g_bar_epoch < barNo) __nanosleep(32);
      }
    }
    __syncthreads();
    __threadfence();
  };

  auto step = [&](const uint2* __restrict__ p0, int A0Q,
                  const uint2* __restrict__ p1, int A1Q,
                  const uint2* __restrict__ Wq, int totQ,
                  const float* __restrict__ scW,
                  const float* __restrict__ xPtr, int Kx,
                  const float* __restrict__ WxF,
                  const float* __restrict__ bias, float* __restrict__ cS,
                  uint2* __restrict__ hOutQ) {
    const int S = totQ >> 4;                   // supers of 2 K=32 chunks
    const size_t bWoff = (size_t)colB * totQ;

    auto ISSUE = [&](int si, int st) {
#pragma unroll
      for (int u = 0; u < 2; ++u) {
        const int kb = si * 2 + u;
        const int gq = kb * 8 + quad2;
        const uint2* asrc = (gq < A0Q)
            ? (p0 + (size_t)mG * A0Q + gq)
            : (p1 + (size_t)mG * A1Q + (gq - A0Q));
        const uint32_t dA = sAu + (((st * 2 + u) * 64 + aRow) * 8 + (quad2 ^ fS)) * 8;
        CP_ASYNC16(dA, asrc);
        const uint32_t dB = sBu + (((st * 2 + u) * 64 + aRow) * 8 + (quad2 ^ fS)) * 8;
        CP_ASYNC16(dB, Wq + bWoff + gq);
      }
    };

    int acc1[2][4][4], acc2[2][4][4];
#pragma unroll
    for (int a = 0; a < 2; ++a)
#pragma unroll
      for (int b = 0; b < 4; ++b)
#pragma unroll
        for (int c = 0; c < 4; ++c) { acc1[a][b][c] = 0; acc2[a][b][c] = 0; }

    ISSUE(0, 0); CP_COMMIT();
    ISSUE(1, 1); CP_COMMIT();
    CP_WAIT1();
    __syncthreads();

    for (int s = 0; s < S; ++s) {
      const int st = s & 1;
      const uint2* As = sA + (st * 2 + wk) * 512;
      const uint2* Bs = sB + (st * 2 + wk) * 512;
      uint32_t aD1[2][4], aD2[2][4], bD1[4][2], bD2[4][2];
#pragma unroll
      for (int mt = 0; mt < 2; ++mt) {
        const int r = wm * 32 + mt * 16 + gid;
        const int fr = (r & 2) * 2;
        const uint2 u0 = As[r * 8 + (q ^ fr)];
        const uint2 u1 = As[(r + 8) * 8 + (q ^ fr)];
        const uint2 u2 = As[r * 8 + ((q + 4) ^ fr)];
        const uint2 u3 = As[(r + 8) * 8 + ((q + 4) ^ fr)];
        aD1[mt][0] = u0.x; aD1[mt][1] = u1.x; aD1[mt][2] = u2.x; aD1[mt][3] = u3.x;
        aD2[mt][0] = u0.y; aD2[mt][1] = u1.y; aD2[mt][2] = u2.y; aD2[mt][3] = u3.y;
      }
#pragma unroll
      for (int nt = 0; nt < 4; ++nt) {
        const int n = wn * 32 + nt * 8 + gid;
        const int fn = (n & 2) * 2;
        const uint2 v0 = Bs[n * 8 + (q ^ fn)];
        const uint2 v1 = Bs[n * 8 + ((q + 4) ^ fn)];
        bD1[nt][0] = v0.x; bD1[nt][1] = v1.x;
        bD2[nt][0] = v0.y; bD2[nt][1] = v1.y;
      }
      __syncthreads();
      if (s + 2 < S) ISSUE(s + 2, st);
      CP_COMMIT();
#pragma unroll
      for (int mt = 0; mt < 2; ++mt)
#pragma unroll
        for (int nt = 0; nt < 4; ++nt) {
          mma_s8(acc1[mt][nt], aD1[mt], bD1[nt]);
          mma_s8(acc2[mt][nt], aD1[mt], bD2[nt]);
          mma_s8(acc2[mt][nt], aD2[mt], bD1[nt]);
        }
      CP_WAIT1();
      __syncthreads();
    }
    CP_WAIT0();
    __syncthreads();

    // ---- split-K reduction: wk==1 hands accs to wk==0 partner ----
    int* a1f = &acc1[0][0][0];
    int* a2f = &acc2[0][0][0];
    const int slotr = (((wid >> 1) * 32) + lane) * 32;
    if (wk) {
#pragma unroll
      for (int i = 0; i < 32; ++i) { redA[slotr + i] = a1f[i]; redB[slotr + i] = a2f[i]; }
    }
    __syncthreads();
    if (!wk) {
#pragma unroll
      for (int i = 0; i < 32; ++i) { a1f[i] += redA[slotr + i]; a2f[i] += redB[slotr + i]; }

      // ---- epilogue: per-row dequant + bias + float x-path + activations ----
      const int cWarp = nBase + wn * 32;
      const int mWarp = mBase + wm * 32;
#pragma unroll
      for (int mt = 0; mt < 2; ++mt) {
        const int r0 = mWarp + mt * 16 + gid;
        const int r1 = r0 + 8;
        float x0v[8], x1v[8];
        for (int k = 0; k < Kx; ++k) {
          x0v[k] = xPtr[r0 * Kx + k];
          x1v[k] = xPtr[r1 * Kx + k];
        }
        float h0a[4], h0b[4], h1a[4], h1b[4];
#pragma unroll
        for (int nt = 0; nt < 4; ++nt) {
          const int col0 = cWarp + nt * 8 + 2 * q;
          const int col1 = col0 + 1;
          float xd0 = 0.f, xd1 = 0.f, xd2 = 0.f, xd3 = 0.f;
          for (int k = 0; k < Kx; ++k) {
            const float w0 = WxF[col0 * Kx + k], w1 = WxF[col1 * Kx + k];
            xd0 += x0v[k] * w0; xd1 += x0v[k] * w1;
            xd2 += x1v[k] * w0; xd3 += x1v[k] * w1;
          }
          const float F1a = fmaxf(scW[col0], 1e-20f) * (1.f / 16129.f);
          const float F1b = fmaxf(scW[col1], 1e-20f) * (1.f / 16129.f);
          const float F2a = F1a * (1.f / 254.f);
          const float F2b = F1b * (1.f / 254.f);
          const float bs0 = bias[(col0 & 3) * HID + (col0 >> 2)];
          const float bs1 = bias[(col1 & 3) * HID + (col1 >> 2)];
          float pre0 = F1a * (float)acc1[mt][nt][0] + F2a * (float)acc2[mt][nt][0] + xd0 + bs0;
          float pre1 = F1b * (float)acc1[mt][nt][1] + F2b * (float)acc2[mt][nt][1] + xd1 + bs1;
          float pre2 = F1a * (float)acc1[mt][nt][2] + F2a * (float)acc2[mt][nt][2] + xd2 + bs0;
          float pre3 = F1b * (float)acc1[mt][nt][3] + F2b * (float)acc2[mt][nt][3] + xd3 + bs1;
          const float p0 = __shfl_xor_sync(0xffffffffu, pre0, 1);
          const float p1 = __shfl_xor_sync(0xffffffffu, pre1, 1);
          const float p2 = __shfl_xor_sync(0xffffffffu, pre2, 1);
          const float p3 = __shfl_xor_sync(0xffffffffu, pre3, 1);
          const int j = col0 >> 2;                   // valid on even lanes
          float hn0, hn1;
          {
            const float ig = sigmoidf_(pre0);
            const float fg = sigmoidf_(pre1);
            const float gg = tanhf(p0);
            const float og = sigmoidf_(p1);
            const float cn = fg * cS[r0 * HID + j] + ig * gg;
            if ((lane & 1) == 0) cS[r0 * HID + j] = cn;
            hn0 = og * tanhf(cn);
          }
          {
            const float ig = sigmoidf_(pre2);
            const float fg = sigmoidf_(pre3);
            const float gg = tanhf(p2);
            const float og = sigmoidf_(p3);
            const float cn = fg * cS[r1 * HID + j] + ig * gg;
            if ((lane & 1) == 0) cS[r1 * HID + j] = cn;
            hn1 = og * tanhf(cn);
          }
          h0a[nt] = hn0; h1a[nt] = hn1;
          h0b[nt] = __shfl_xor_sync(0xffffffffu, hn0, 2);
          h1b[nt] = __shfl_xor_sync(0xffffffffu, hn1, 2);
        }
        if (q == 0) {
#pragma unroll
          for (int ntp = 0; ntp < 4; ntp += 2) {
            const int jq = (cWarp + ntp * 8) >> 4;
            hOutQ[(size_t)r0 * HQ + jq] =
                q4pack(h0a[ntp] * 127.f, h0b[ntp] * 127.f,
                       h0a[ntp + 1] * 127.f, h0b[ntp + 1] * 127.f);
            hOutQ[(size_t)r1 * HQ + jq] =
                q4pack(h1a[ntp] * 127.f, h1b[ntp] * 127.f,
                       h1a[ntp + 1] * 127.f, h1b[ntp + 1] * 127.f);
          }
        }
      }
    }
  };

  const size_t HSQ = (size_t)NB * HQ;

  // -------- encoder layer 0 (h-GEMM K=1024, x via float path Kx=8) --------
  for (int t = 0; t < TSTEPS; ++t) {
    const uint2* ph = t ? (g_ys0q + (size_t)(t - 1) * HSQ) : g_zq;
    step(ph, HQ, g_zq, HQ, g_Wq_e0, HQ, g_scW,
         g_xf + (size_t)t * NB * 8, 8, g_We0xF, eb0, g_c0,
         g_ys0q + (size_t)t * HSQ);
    grid_barrier();
  }
  // -------- encoder layer 1 ([ys0|h] K=2048) --------
  for (int t = 0; t < TSTEPS; ++t) {
    const int cur = t & 1, prv = (t - 1) & 1;
    const uint2* ph = t ? (g_hBq + (size_t)prv * HSQ) : g_zq;
    step(g_ys0q + (size_t)t * HSQ, HQ, ph, HQ, g_Wq_e1, Q1, g_scW + 4096,
         g_predf, 0, g_Wd0xF, eb1, g_c1, g_hBq + (size_t)cur * HSQ);
    grid_barrier();
  }
  // -------- decoder --------
  for (int t = 0; t < HORIZON; ++t) {
    const int cur = t & 1, prv = (t - 1) & 1;
    const uint2* ph0 = t ? (g_hd0q + (size_t)prv * HSQ)
                         : (g_ys0q + (size_t)(TSTEPS - 1) * HSQ);
    step(ph0, HQ, g_zq, HQ, g_Wq_d0, HQ, g_scW + 2 * 4096,
         g_predf, 1, g_Wd0xF, db0, g_c0, g_hd0q + (size_t)cur * HSQ);
    grid_barrier();
    const uint2* ph1 = t ? (g_hd1q + (size_t)prv * HSQ) : (g_hBq + HSQ);
    step(g_hd0q + (size_t)cur * HSQ, HQ, ph1, HQ, g_Wq_d1, Q1, g_scW + 3 * 4096,
         g_predf, 0, g_Wd0xF, db1, g_c1, g_hd1q + (size_t)cur * HSQ);
    grid_barrier();
    // projection: CTA bx handles batch row bx (dequant h1)
    {
      const uint2* hr = g_hd1q + (size_t)cur * HSQ + (size_t)bx * HQ;
      float s = 0.f;
      for (int p = tid; p < HQ; p += NTHR) {
        const uint2 u = hr[p];
#pragma unroll
        for (int i = 0; i < 4; ++i) {
          const float v = ((float)s8at(u.x, i) + (float)s8at(u.y, i) * (1.f / 254.f)) *
                          (1.f / 127.f);
          s += v * projW[4 * p + i];
        }
      }
#pragma unroll
      for (int o = 16; o; o >>= 1) s += __shfl_xor_sync(0xffffffffu, s, o);
      if (lane == 0) redF[wid] = s;
      __syncthreads();
      if (tid == 0) {
        float tot = 0.f;
#pragma unroll
        for (int i = 0; i < 8; ++i) tot += redF[i];
        const float p = tot + projb[0];
        out[bx * HORIZON + t] = p;
        g_predf[bx] = p;
      }
      __syncthreads();
    }
    grid_barrier();
  }
}

// ---------------- per-row scale prepass (deterministic, no atomics) --------------
// thread t handles (matrix sIdx = t>>12, interleaved col = t&4095): serial row max.
__global__ void scale_kernel(
    const float* __restrict__ eWhh0, const float* __restrict__ eWih1,
    const float* __restrict__ eWhh1, const float* __restrict__ dWhh0,
    const float* __restrict__ dWih1, const float* __restrict__ dWhh1)
{
  const int t = blockIdx.x * blockDim.x + threadIdx.x;
  if (t >= 4 * 4096) return;
  const int sIdx = t >> 12;
  const int col  = t & 4095;
  const int orow = (col & 3) * HID + (col >> 2);
  float m = 0.f;
  if (sIdx == 0) {
    const float* w = eWhh0 + (size_t)orow * HID;
    for (int k = 0; k < HID; ++k) m = fmaxf(m, fabsf(w[k]));
  } else if (sIdx == 1) {
    const float* wa = eWih1 + (size_t)orow * HID;
    const float* wb = eWhh1 + (size_t)orow * HID;
    for (int k = 0; k < HID; ++k) m = fmaxf(m, fmaxf(fabsf(wa[k]), fabsf(wb[k])));
  } else if (sIdx == 2) {
    const float* w = dWhh0 + (size_t)orow * HID;
    for (int k = 0; k < HID; ++k) m = fmaxf(m, fabsf(w[k]));
  } else {
    const float* wa = dWih1 + (size_t)orow * HID;
    const float* wb = dWhh1 + (size_t)orow * HID;
    for (int k = 0; k < HID; ++k) m = fmaxf(m, fmaxf(fabsf(wa[k]), fabsf(wb[k])));
  }
  g_scW[t] = m;
}

// ---------------- init: quantize weights (per-row scale), stage x, zeros ---------
__global__ void init_kernel(
    const float* __restrict__ x,
    const float* __restrict__ eWih0, const float* __restrict__ eWhh0,
    const float* __restrict__ eWih1, const float* __restrict__ eWhh1,
    const float* __restrict__ dWih0, const float* __restrict__ dWhh0,
    const float* __restrict__ dWih1, const float* __restrict__ dWhh1)
{
  const int nth = gridDim.x * blockDim.x;
  const int t0 = blockIdx.x * blockDim.x + threadIdx.x;
  if (t0 == 0) { g_bar_cnt = 0; g_bar_epoch = 0; }

  // e0/d0: Whh only, K=1024 (HQ quads)
  for (size_t i = t0; i < (size_t)4096 * HQ; i += nth) {
    const int c = (int)(i / HQ);
    const int gq = (int)(i % HQ);
    const int orow = (c & 3) * HID + (c >> 2);
    const int k = gq * 4;
    const float is0 = 127.f / fmaxf(g_scW[c], 1e-20f);
    const float is2 = 127.f / fmaxf(g_scW[2 * 4096 + c], 1e-20f);
    const float* we = eWhh0 + (size_t)orow * HID + k;
    const float* wd = dWhh0 + (size_t)orow * HID + k;
    g_Wq_e0[i] = q4pack(we[0] * is0, we[1] * is0, we[2] * is0, we[3] * is0);
    g_Wq_d0[i] = q4pack(wd[0] * is2, wd[1] * is2, wd[2] * is2, wd[3] * is2);
  }
  // e1/d1: [Wih|Whh], K=2048 (Q1 quads)
  for (size_t i = t0; i < (size_t)4096 * Q1; i += nth) {
    const int c = (int)(i / Q1);
    const int gq = (int)(i % Q1);
    const int orow = (c & 3) * HID + (c >> 2);
    const float is1 = 127.f / fmaxf(g_scW[4096 + c], 1e-20f);
    const float is3 = 127.f / fmaxf(g_scW[3 * 4096 + c], 1e-20f);
    const float* we;
    const float* wd;
    if (gq < HQ) {
      we = eWih1 + (size_t)orow * HID + gq * 4;
      wd = dWih1 + (size_t)orow * HID + gq * 4;
    } else {
      we = eWhh1 + (size_t)orow * HID + (gq - HQ) * 4;
      wd = dWhh1 + (size_t)orow * HID + (gq - HQ) * 4;
    }
    g_Wq_e1[i] = q4pack(we[0] * is1, we[1] * is1, we[2] * is1, we[3] * is1);
    g_Wq_d1[i] = q4pack(wd[0] * is3, wd[1] * is3, wd[2] * is3, wd[3] * is3);
  }
  // x-path float weights
  for (int i = t0; i < 4096 * 8; i += nth) {
    const int c = i >> 3, k = i & 7;
    const int orow = (c & 3) * HID + (c >> 2);
    g_We0xF[i] = eWih0[orow * 8 + k];
    if (k == 0) g_Wd0xF[c] = dWih0[orow];
  }
  // x floats [t][m][8]
  for (size_t i = t0; i < (size_t)TSTEPS * NB * 8; i += nth) {
    const int k = (int)(i & 7);
    const int m = (int)((i >> 3) & (NB - 1));
    const int t = (int)(i >> 10);
    g_xf[i] = x[((size_t)m * TSTEPS + t) * 8 + k];
  }
  for (int i = t0; i < NB; i += nth)
    g_predf[i] = x[((size_t)i * TSTEPS + (TSTEPS - 1)) * 8];
  for (size_t i = t0; i < (size_t)NB * HQ; i += nth) g_zq[i] = make_uint2(0u, 0u);
  for (int i = t0; i < NB * HID; i += nth) { g_c0[i] = 0.f; g_c1[i] = 0.f; }
}

// ---------------- host side ------------------------------------------------------
extern "C" void kernel_launch(void* const* d_in, const int* in_sizes, int n_in,
                              void* d_out, int out_size) {
  const float* x     = (const float*)d_in[0];
  const float* eWih0 = (const float*)d_in[1];
  const float* eWhh0 = (const float*)d_in[2];
  const float* eb0   = (const float*)d_in[3];
  const float* eWih1 = (const float*)d_in[4];
  const float* eWhh1 = (const float*)d_in[5];
  const float* eb1   = (const float*)d_in[6];
  const float* dWih0 = (const float*)d_in[7];
  const float* dWhh0 = (const float*)d_in[8];
  const float* db0   = (const float*)d_in[9];
  const float* dWih1 = (const float*)d_in[10];
  const float* dWhh1 = (const float*)d_in[11];
  const float* db1   = (const float*)d_in[12];
  const float* projW = (const float*)d_in[13];
  const float* projb = (const float*)d_in[14];
  float* out = (float*)d_out;

  scale_kernel<<<64, 256>>>(eWhh0, eWih1, eWhh1, dWhh0, dWih1, dWhh1);
  init_kernel<<<4096, 512>>>(x, eWih0, eWhh0, eWih1, eWhh1,
                             dWih0, dWhh0, dWih1, dWhh1);
  lstm_persist<<<NCTA, NTHR>>>(eb0, eb1, db0, db1, projW, projb, out);
}